// round 8
// baseline (speedup 1.0000x reference)
#include <cuda_runtime.h>
#include <cstdint>

#define NT   256
#define BP   128
#define STR  132            // padded SMEM row stride in words (16B-aligned rows)
#define OMEGA 30.0f

typedef unsigned long long ull;

// ---------------- f32x2 packed-FMA helpers (sm_100+) ----------------
__device__ __forceinline__ ull fma2(ull a, ull b, ull c) {
    ull d;
    asm("fma.rn.f32x2 %0, %1, %2, %3;" : "=l"(d) : "l"(a), "l"(b), "l"(c));
    return d;
}
__device__ __forceinline__ ull dup2(float x) {
    ull d; unsigned u = __float_as_uint(x);
    asm("mov.b64 %0, {%1, %1};" : "=l"(d) : "r"(u));
    return d;
}
__device__ __forceinline__ ull pack2(float a, float b) {
    ull d;
    asm("mov.b64 %0, {%1, %2};" : "=l"(d) : "r"(__float_as_uint(a)), "r"(__float_as_uint(b)));
    return d;
}
__device__ __forceinline__ float lo2(ull a) { return __uint_as_float((unsigned)a); }
__device__ __forceinline__ float hi2(ull a) { return __uint_as_float((unsigned)(a >> 32)); }

// 16B shared loads/stores as pre-paired 64-bit regs (no struct shuffling)
__device__ __forceinline__ void lds128(ull& x, ull& y, const float* p) {
    unsigned a = (unsigned)__cvta_generic_to_shared(p);
    asm("ld.shared.v2.b64 {%0, %1}, [%2];" : "=l"(x), "=l"(y) : "r"(a));
}
__device__ __forceinline__ void sts128(float* p, ull x, ull y) {
    unsigned a = (unsigned)__cvta_generic_to_shared(p);
    asm("st.shared.v2.b64 [%0], {%1, %2};" :: "r"(a), "l"(x), "l"(y) : "memory");
}

// ---------------- branchless sin(30*u + b30), fast-math-proof ----------------
__device__ __forceinline__ float sin_omb(float u, float b30) {
    float x  = fmaf(u, OMEGA, b30);
    float nf = fmaf(x, 0.318309886183790672f, 12582912.0f);   // 1.5*2^23 magic
    unsigned nb = __float_as_uint(nf);
    float n  = nf - 12582912.0f;                              // exact rint(x/pi)
    float r  = fmaf(n, -3.140625f,             x);
    r        = fmaf(n, -9.670257568359375e-4f, r);
    r        = fmaf(n, -6.27832957e-7f,        r);
    float r2 = r * r;
    float p  = -2.50521084e-8f;
    p = fmaf(p, r2,  2.75573192e-6f);
    p = fmaf(p, r2, -1.98412698e-4f);
    p = fmaf(p, r2,  8.33333333e-3f);
    p = fmaf(p, r2, -1.66666667e-1f);
    float s  = fmaf(p * r2, r, r);
    return __uint_as_float(__float_as_uint(s) ^ (nb << 31));  // flip sign if n odd
}

// ---------------- accurate scalar sincos (positional encoding only) ----------------
__device__ __forceinline__ float sin_poly(float r) {
    float r2 = r * r;
    float p = -2.50521084e-8f;
    p = fmaf(p, r2,  2.75573192e-6f);
    p = fmaf(p, r2, -1.98412698e-4f);
    p = fmaf(p, r2,  8.33333333e-3f);
    p = fmaf(p, r2, -1.66666667e-1f);
    return fmaf(p * r2, r, r);
}
__device__ __forceinline__ float cos_poly(float r) {
    float r2 = r * r;
    float p =  2.08767570e-9f;
    p = fmaf(p, r2, -2.75573192e-7f);
    p = fmaf(p, r2,  2.48015873e-5f);
    p = fmaf(p, r2, -1.38888889e-3f);
    p = fmaf(p, r2,  4.16666667e-2f);
    p = fmaf(p, r2, -0.5f);
    return fmaf(p, r2, 1.0f);
}
__device__ __forceinline__ void sincos_acc(float x, float* so, float* co) {
    float n = rintf(x * 0.318309886183790672f);
    float r = fmaf(n, -3.140625f,             x);
    r       = fmaf(n, -9.670257568359375e-4f, r);
    r       = fmaf(n, -6.27832957e-7f,        r);
    int par = ((int)n) & 1;
    float s = sin_poly(r), c = cos_poly(r);
    if (par) { s = -s; c = -c; }
    *so = s; *co = c;
}

// ---------------- 128-wide sine layer ----------------
// out[j][p] = sin(30*(sum_k in[k][p]*W[k][j]) + 30*b[j])
// Warp: 8 consecutive jg x 4 consecutive pg. Weight LDG.128 span 256B (2 lines each);
// act LDS.128: 4 distinct 16B within a 128B segment -> 1 wavefront each.
template <int K>
__device__ __forceinline__ void big_layer(const float* __restrict__ sInB, float* __restrict__ sOut,
                                          const float* __restrict__ Wg, const float* __restrict__ bg,
                                          int jg, int pg) {
    const float*  ip = sInB + (pg << 3);
    const float4* wp = (const float4*)Wg;   // row k: quads [k*32 + jg*2], [k*32 + jg*2 + 1]
    ull acc[32];
#pragma unroll
    for (int i = 0; i < 32; i++) acc[i] = 0ull;

#pragma unroll 4
    for (int k = 0; k < K; k++) {
        const float* a = ip + k * STR;
        ull ap[4];
        lds128(ap[0], ap[1], a);
        lds128(ap[2], ap[3], a + 4);
        float4 wA = __ldg(wp + k * 32 + (jg << 1));
        float4 wB = __ldg(wp + k * 32 + (jg << 1) + 1);
        ull wq[8];
        wq[0] = dup2(wA.x); wq[1] = dup2(wA.y); wq[2] = dup2(wA.z); wq[3] = dup2(wA.w);
        wq[4] = dup2(wB.x); wq[5] = dup2(wB.y); wq[6] = dup2(wB.z); wq[7] = dup2(wB.w);
#pragma unroll
        for (int jj = 0; jj < 8; jj++)
#pragma unroll
            for (int pp = 0; pp < 4; pp++)
                acc[jj * 4 + pp] = fma2(ap[pp], wq[jj], acc[jj * 4 + pp]);
    }
    __syncthreads();   // all reads of sIn done before anyone overwrites sOut (may alias sIn)

    const int j0 = jg << 3, p0 = pg << 3;
#pragma unroll
    for (int jj = 0; jj < 8; jj++) {
        float b30 = OMEGA * __ldg(bg + j0 + jj);
        float* orow = sOut + (j0 + jj) * STR + p0;
        ull o0 = pack2(sin_omb(lo2(acc[jj * 4 + 0]), b30), sin_omb(hi2(acc[jj * 4 + 0]), b30));
        ull o1 = pack2(sin_omb(lo2(acc[jj * 4 + 1]), b30), sin_omb(hi2(acc[jj * 4 + 1]), b30));
        ull o2 = pack2(sin_omb(lo2(acc[jj * 4 + 2]), b30), sin_omb(hi2(acc[jj * 4 + 2]), b30));
        ull o3 = pack2(sin_omb(lo2(acc[jj * 4 + 3]), b30), sin_omb(hi2(acc[jj * 4 + 3]), b30));
        sts128(orow,     o0, o1);
        sts128(orow + 4, o2, o3);
    }
    __syncthreads();   // epilogue done before next layer's mainloop overwrites inputs
}

// SMEM floats: sAct 128*STR | sE 78*STR   (~109 KB -> 2 CTAs/SM)
#define SMEM_WORDS ((128 + 78) * STR)

__global__ void __launch_bounds__(NT, 2)
siren_kernel(const float* __restrict__ pts,
             const float* __restrict__ W0, const float* __restrict__ b0,
             const float* __restrict__ W1, const float* __restrict__ b1,
             const float* __restrict__ W2, const float* __restrict__ b2,
             const float* __restrict__ W3, const float* __restrict__ b3,
             const float* __restrict__ W4, const float* __restrict__ b4,
             const float* __restrict__ W5, const float* __restrict__ b5,
             const float* __restrict__ W6, const float* __restrict__ b6,
             const float* __restrict__ W7, const float* __restrict__ b7,
             float* __restrict__ out, int n) {
    extern __shared__ float sm[];
    float* sAct = sm;                    // [128][STR]
    float* sE   = sAct + 128 * STR;      // [78][STR]: rows 0..14 scalar, 15..17 x, 18..77 trig enc

    const int tid = threadIdx.x;
    const int pbase = blockIdx.x * BP;
    const int w = tid >> 5, l = tid & 31;
    const int jg = ((w & 1) << 3) | (l & 7);        // 8 consecutive jg per warp
    const int pg = ((w >> 1) << 2) | (l >> 3);      // 4 consecutive pg per warp

    // ---------------- positional encoding ----------------
    for (int idx = tid; idx < BP * 3; idx += NT) {
        int p = idx / 3, c = idx - 3 * p;
        sE[(15 + c) * STR + p] = pts[pbase * 3 + idx];
    }
    __syncthreads();
    for (int t = tid; t < BP * 30; t += NT) {
        int p = t & (BP - 1);
        int i = t >> 7;                 // 0..29
        int f = i / 3, c = i - 3 * f;
        float freq = 3.14159265358979323846f * (float)(1 << f);
        float ang = sE[(15 + c) * STR + p] * freq;
        float s, co; sincos_acc(ang, &s, &co);
        sE[(18 + 6 * f + c) * STR + p] = s;
        sE[(21 + 6 * f + c) * STR + p] = co;
    }
    __syncthreads();

    // ---------------- L0: enc(63) -> 128 ----------------
    big_layer<63>(sE + 15 * STR, sAct, W0, b0, jg, pg);
    // ---------------- L1..L3: 128 -> 128 ----------------
    big_layer<128>(sAct, sAct, W1, b1, jg, pg);
    big_layer<128>(sAct, sAct, W2, b2, jg, pg);
    big_layer<128>(sAct, sAct, W3, b3, jg, pg);

    // ---------------- L4: 128 -> 16, no activation; j0 -> density, j1..15 -> scalar ----------------
    {
        const int j = tid & 15, pq = tid >> 4;
        const float* ip = sAct + (pq << 3);
        ull a4[4] = {0ull, 0ull, 0ull, 0ull};
#pragma unroll 4
        for (int k = 0; k < 128; k++) {
            const float* a = ip + k * STR;
            ull x0, x1, x2, x3;
            lds128(x0, x1, a);
            lds128(x2, x3, a + 4);
            ull w4v = dup2(__ldg(W4 + (k << 4) + j));
            a4[0] = fma2(x0, w4v, a4[0]);
            a4[1] = fma2(x1, w4v, a4[1]);
            a4[2] = fma2(x2, w4v, a4[2]);
            a4[3] = fma2(x3, w4v, a4[3]);
        }
        float bj = __ldg(b4 + j);
        if (j == 0) {
            float* od = out + n + pbase + (pq << 3);   // density block
#pragma unroll
            for (int q = 0; q < 4; q++) {
                od[2 * q]     = fmaxf(lo2(a4[q]) + bj, 0.0f);
                od[2 * q + 1] = fmaxf(hi2(a4[q]) + bj, 0.0f);
            }
        } else {
            float* orow = sE + (j - 1) * STR + (pq << 3);   // scalar features, rows 0..14
            ull s0 = pack2(lo2(a4[0]) + bj, hi2(a4[0]) + bj);
            ull s1 = pack2(lo2(a4[1]) + bj, hi2(a4[1]) + bj);
            ull s2 = pack2(lo2(a4[2]) + bj, hi2(a4[2]) + bj);
            ull s3 = pack2(lo2(a4[3]) + bj, hi2(a4[3]) + bj);
            sts128(orow,     s0, s1);
            sts128(orow + 4, s2, s3);
        }
        __syncthreads();
    }

    // ---------------- L5: [scalar(15) | enc(63)] = 78 -> 128 ----------------
    big_layer<78>(sE, sAct, W5, b5, jg, pg);
    // ---------------- L6: 128 -> 128 ----------------
    big_layer<128>(sAct, sAct, W6, b6, jg, pg);

    // ---------------- L7: 128 -> 1 ----------------
    if (tid < BP) {
        float acc = 0.0f;
#pragma unroll 8
        for (int k = 0; k < 128; k++)
            acc = fmaf(sAct[k * STR + tid], __ldg(W7 + k), acc);
        out[pbase + tid] = acc + __ldg(b7);
    }
}

extern "C" void kernel_launch(void* const* d_in, const int* in_sizes, int n_in,
                              void* d_out, int out_size) {
    (void)n_in; (void)out_size;
    const float* pts = (const float*)d_in[0];
    const float* W0 = (const float*)d_in[1];  const float* b0 = (const float*)d_in[2];
    const float* W1 = (const float*)d_in[3];  const float* b1 = (const float*)d_in[4];
    const float* W2 = (const float*)d_in[5];  const float* b2 = (const float*)d_in[6];
    const float* W3 = (const float*)d_in[7];  const float* b3 = (const float*)d_in[8];
    const float* W4 = (const float*)d_in[9];  const float* b4 = (const float*)d_in[10];
    const float* W5 = (const float*)d_in[11]; const float* b5 = (const float*)d_in[12];
    const float* W6 = (const float*)d_in[13]; const float* b6 = (const float*)d_in[14];
    const float* W7 = (const float*)d_in[15]; const float* b7 = (const float*)d_in[16];
    float* out = (float*)d_out;

    int n = in_sizes[0] / 3;
    int blocks = n / BP;
    size_t shmem = (size_t)SMEM_WORDS * sizeof(float);   // ~109 KB -> 2 CTAs/SM

    cudaFuncSetAttribute(siren_kernel, cudaFuncAttributeMaxDynamicSharedMemorySize, (int)shmem);
    siren_kernel<<<blocks, NT, shmem>>>(pts, W0, b0, W1, b1, W2, b2, W3, b3,
                                        W4, b4, W5, b5, W6, b6, W7, b7, out, n);
}

// round 9
// speedup vs baseline: 1.0482x; 1.0482x over previous
#include <cuda_runtime.h>
#include <cstdint>

#define NT   256
#define BP   128
#define STR  130            // padded SMEM row stride in words (8B-aligned, conflict-free)
#define OMEGA 30.0f

typedef unsigned long long ull;

// ---------------- f32x2 packed-FMA helpers (sm_100+) ----------------
__device__ __forceinline__ ull fma2(ull a, ull b, ull c) {
    ull d;
    asm("fma.rn.f32x2 %0, %1, %2, %3;" : "=l"(d) : "l"(a), "l"(b), "l"(c));
    return d;
}
__device__ __forceinline__ ull dup2(float x) {
    ull d; unsigned u = __float_as_uint(x);
    asm("mov.b64 %0, {%1, %1};" : "=l"(d) : "r"(u));
    return d;
}
__device__ __forceinline__ ull pack2(float a, float b) {
    ull d;
    asm("mov.b64 %0, {%1, %2};" : "=l"(d) : "r"(__float_as_uint(a)), "r"(__float_as_uint(b)));
    return d;
}
__device__ __forceinline__ float lo2(ull a) { return __uint_as_float((unsigned)a); }
__device__ __forceinline__ float hi2(ull a) { return __uint_as_float((unsigned)(a >> 32)); }

__device__ __forceinline__ float mufu_sin(float r) {
    float s;
    asm("sin.approx.f32 %0, %1;" : "=f"(s) : "f"(r));
    return s;
}
__device__ __forceinline__ float mufu_cos(float r) {
    float c;
    asm("cos.approx.f32 %0, %1;" : "=f"(c) : "f"(r));
    return c;
}

// ---------------- branchless sin(30*u + b30) ----------------
// 5 immediate-form FFMAs (reduction) + 1 MUFU.SIN on r in [-pi/2, pi/2] (+eps)
// + parity sign via XOR. MUFU abs err ~2^-21.4 on reduced range. Fast-math-proof.
__device__ __forceinline__ float sin_omb(float u, float b30) {
    float x  = fmaf(u, OMEGA, b30);
    float nf = fmaf(x, 0.318309886183790672f, 12582912.0f);   // 1.5*2^23 magic
    unsigned nb = __float_as_uint(nf);
    float n  = nf - 12582912.0f;                              // exact rint(x/pi)
    float r  = fmaf(n, -3.140625f,             x);
    r        = fmaf(n, -9.670257568359375e-4f, r);
    r        = fmaf(n, -6.27832957e-7f,        r);
    float s  = mufu_sin(r);
    return __uint_as_float(__float_as_uint(s) ^ (nb << 31));  // flip sign if n odd
}

// ---------------- sincos for positional encoding (same reduction + 2 MUFU) ----------------
__device__ __forceinline__ void sincos_acc(float x, float* so, float* co) {
    float nf = fmaf(x, 0.318309886183790672f, 12582912.0f);
    unsigned sgn = __float_as_uint(nf) << 31;                 // parity of n
    float n  = nf - 12582912.0f;
    float r  = fmaf(n, -3.140625f,             x);
    r        = fmaf(n, -9.670257568359375e-4f, r);
    r        = fmaf(n, -6.27832957e-7f,        r);
    *so = __uint_as_float(__float_as_uint(mufu_sin(r)) ^ sgn);
    *co = __uint_as_float(__float_as_uint(mufu_cos(r)) ^ sgn);
}

// ---------------- 128-wide sine layer ----------------
// out[j][p] = sin(30*(sum_k in[k][p]*W[k][j]) + 30*b[j])
// Warp covers 8 consecutive jg x 4 consecutive pg -> weight LDG.128 span 256B (2 lines),
// act LDS.64 hits 4 distinct 8B on banks {0,8,16,24} (conflict-free broadcast).
template <int K>
__device__ __forceinline__ void big_layer(const float* __restrict__ sInB, float* __restrict__ sOut,
                                          const float* __restrict__ Wg, const float* __restrict__ bg,
                                          int jg, int pg) {
    const float*  ip = sInB + (pg << 3);
    const float4* wp = (const float4*)Wg;   // row k: quads [k*32 + jg*2], [k*32 + jg*2 + 1]
    ull acc[32];
#pragma unroll
    for (int i = 0; i < 32; i++) acc[i] = 0ull;

#pragma unroll 4
    for (int k = 0; k < K; k++) {
        const float* a = ip + k * STR;
        ull ap[4];
        ap[0] = *(const ull*)(a);
        ap[1] = *(const ull*)(a + 2);
        ap[2] = *(const ull*)(a + 4);
        ap[3] = *(const ull*)(a + 6);
        float4 wA = __ldg(wp + k * 32 + (jg << 1));
        float4 wB = __ldg(wp + k * 32 + (jg << 1) + 1);
        ull wq[8];
        wq[0] = dup2(wA.x); wq[1] = dup2(wA.y); wq[2] = dup2(wA.z); wq[3] = dup2(wA.w);
        wq[4] = dup2(wB.x); wq[5] = dup2(wB.y); wq[6] = dup2(wB.z); wq[7] = dup2(wB.w);
#pragma unroll
        for (int jj = 0; jj < 8; jj++)
#pragma unroll
            for (int pp = 0; pp < 4; pp++)
                acc[jj * 4 + pp] = fma2(ap[pp], wq[jj], acc[jj * 4 + pp]);
    }
    __syncthreads();   // all reads of sIn done before anyone overwrites sOut (may alias sIn)

    const int j0 = jg << 3, p0 = pg << 3;
#pragma unroll
    for (int jj = 0; jj < 8; jj++) {
        float b30 = OMEGA * __ldg(bg + j0 + jj);
        float* orow = sOut + (j0 + jj) * STR + p0;
#pragma unroll
        for (int pp = 0; pp < 4; pp++) {
            float v0 = sin_omb(lo2(acc[jj * 4 + pp]), b30);
            float v1 = sin_omb(hi2(acc[jj * 4 + pp]), b30);
            *(ull*)(orow + 2 * pp) = pack2(v0, v1);
        }
    }
    __syncthreads();   // epilogue done before next layer's mainloop overwrites inputs
}

// SMEM floats: sAct 128*STR | sE 78*STR   (~107 KB -> 2 CTAs/SM)
#define SMEM_WORDS ((128 + 78) * STR)

__global__ void __launch_bounds__(NT, 2)
siren_kernel(const float* __restrict__ pts,
             const float* __restrict__ W0, const float* __restrict__ b0,
             const float* __restrict__ W1, const float* __restrict__ b1,
             const float* __restrict__ W2, const float* __restrict__ b2,
             const float* __restrict__ W3, const float* __restrict__ b3,
             const float* __restrict__ W4, const float* __restrict__ b4,
             const float* __restrict__ W5, const float* __restrict__ b5,
             const float* __restrict__ W6, const float* __restrict__ b6,
             const float* __restrict__ W7, const float* __restrict__ b7,
             float* __restrict__ out, int n) {
    extern __shared__ float sm[];
    float* sAct = sm;                    // [128][STR]
    float* sE   = sAct + 128 * STR;      // [78][STR]: rows 0..14 scalar, 15..17 x, 18..77 trig enc

    const int tid = threadIdx.x;
    const int pbase = blockIdx.x * BP;
    const int w = tid >> 5, l = tid & 31;
    const int jg = ((w & 1) << 3) | (l & 7);        // 8 consecutive jg per warp
    const int pg = ((w >> 1) << 2) | (l >> 3);      // 4 consecutive pg per warp

    // ---------------- positional encoding ----------------
    for (int idx = tid; idx < BP * 3; idx += NT) {
        int p = idx / 3, c = idx - 3 * p;
        sE[(15 + c) * STR + p] = pts[pbase * 3 + idx];
    }
    __syncthreads();
    for (int t = tid; t < BP * 30; t += NT) {
        int p = t & (BP - 1);
        int i = t >> 7;                 // 0..29
        int f = i / 3, c = i - 3 * f;
        float freq = 3.14159265358979323846f * (float)(1 << f);
        float ang = sE[(15 + c) * STR + p] * freq;
        float s, co; sincos_acc(ang, &s, &co);
        sE[(18 + 6 * f + c) * STR + p] = s;
        sE[(21 + 6 * f + c) * STR + p] = co;
    }
    __syncthreads();

    // ---------------- L0: enc(63) -> 128 ----------------
    big_layer<63>(sE + 15 * STR, sAct, W0, b0, jg, pg);
    // ---------------- L1..L3: 128 -> 128 ----------------
    big_layer<128>(sAct, sAct, W1, b1, jg, pg);
    big_layer<128>(sAct, sAct, W2, b2, jg, pg);
    big_layer<128>(sAct, sAct, W3, b3, jg, pg);

    // ---------------- L4: 128 -> 16, no activation; j0 -> density, j1..15 -> scalar ----------------
    {
        const int j = tid & 15, pq = tid >> 4;
        const float* ip = sAct + (pq << 3);
        ull a4[4] = {0ull, 0ull, 0ull, 0ull};
#pragma unroll 4
        for (int k = 0; k < 128; k++) {
            const float* a = ip + k * STR;
            ull x0 = *(const ull*)(a);
            ull x1 = *(const ull*)(a + 2);
            ull x2 = *(const ull*)(a + 4);
            ull x3 = *(const ull*)(a + 6);
            ull w4v = dup2(__ldg(W4 + (k << 4) + j));
            a4[0] = fma2(x0, w4v, a4[0]);
            a4[1] = fma2(x1, w4v, a4[1]);
            a4[2] = fma2(x2, w4v, a4[2]);
            a4[3] = fma2(x3, w4v, a4[3]);
        }
        float bj = __ldg(b4 + j);
        if (j == 0) {
            float* od = out + n + pbase + (pq << 3);   // density block
#pragma unroll
            for (int q = 0; q < 4; q++) {
                od[2 * q]     = fmaxf(lo2(a4[q]) + bj, 0.0f);
                od[2 * q + 1] = fmaxf(hi2(a4[q]) + bj, 0.0f);
            }
        } else {
            float* orow = sE + (j - 1) * STR + (pq << 3);   // scalar features, rows 0..14
#pragma unroll
            for (int q = 0; q < 4; q++)
                *(ull*)(orow + 2 * q) = pack2(lo2(a4[q]) + bj, hi2(a4[q]) + bj);
        }
        __syncthreads();
    }

    // ---------------- L5: [scalar(15) | enc(63)] = 78 -> 128 ----------------
    big_layer<78>(sE, sAct, W5, b5, jg, pg);
    // ---------------- L6: 128 -> 128 ----------------
    big_layer<128>(sAct, sAct, W6, b6, jg, pg);

    // ---------------- L7: 128 -> 1 ----------------
    if (tid < BP) {
        float acc = 0.0f;
#pragma unroll 8
        for (int k = 0; k < 128; k++)
            acc = fmaf(sAct[k * STR + tid], __ldg(W7 + k), acc);
        out[pbase + tid] = acc + __ldg(b7);
    }
}

extern "C" void kernel_launch(void* const* d_in, const int* in_sizes, int n_in,
                              void* d_out, int out_size) {
    (void)n_in; (void)out_size;
    const float* pts = (const float*)d_in[0];
    const float* W0 = (const float*)d_in[1];  const float* b0 = (const float*)d_in[2];
    const float* W1 = (const float*)d_in[3];  const float* b1 = (const float*)d_in[4];
    const float* W2 = (const float*)d_in[5];  const float* b2 = (const float*)d_in[6];
    const float* W3 = (const float*)d_in[7];  const float* b3 = (const float*)d_in[8];
    const float* W4 = (const float*)d_in[9];  const float* b4 = (const float*)d_in[10];
    const float* W5 = (const float*)d_in[11]; const float* b5 = (const float*)d_in[12];
    const float* W6 = (const float*)d_in[13]; const float* b6 = (const float*)d_in[14];
    const float* W7 = (const float*)d_in[15]; const float* b7 = (const float*)d_in[16];
    float* out = (float*)d_out;

    int n = in_sizes[0] / 3;
    int blocks = n / BP;
    size_t shmem = (size_t)SMEM_WORDS * sizeof(float);   // ~107 KB -> 2 CTAs/SM

    cudaFuncSetAttribute(siren_kernel, cudaFuncAttributeMaxDynamicSharedMemorySize, (int)shmem);
    siren_kernel<<<blocks, NT, shmem>>>(pts, W0, b0, W1, b1, W2, b2, W3, b3,
                                        W4, b4, W5, b5, W6, b6, W7, b7, out, n);
}

// round 10
// speedup vs baseline: 1.0496x; 1.0013x over previous
#include <cuda_runtime.h>
#include <cstdint>

#define NT   256
#define BP   128
#define STR  130            // padded SMEM row stride in words (8B-aligned, conflict-free)
#define OMEGA 30.0f

typedef unsigned long long ull;

// ---------------- f32x2 packed-FMA helpers (sm_100+) ----------------
__device__ __forceinline__ ull fma2(ull a, ull b, ull c) {
    ull d;
    asm("fma.rn.f32x2 %0, %1, %2, %3;" : "=l"(d) : "l"(a), "l"(b), "l"(c));
    return d;
}
__device__ __forceinline__ ull dup2(float x) {
    ull d; unsigned u = __float_as_uint(x);
    asm("mov.b64 %0, {%1, %1};" : "=l"(d) : "r"(u));
    return d;
}
__device__ __forceinline__ ull pack2(float a, float b) {
    ull d;
    asm("mov.b64 %0, {%1, %2};" : "=l"(d) : "r"(__float_as_uint(a)), "r"(__float_as_uint(b)));
    return d;
}
__device__ __forceinline__ float lo2(ull a) { return __uint_as_float((unsigned)a); }
__device__ __forceinline__ float hi2(ull a) { return __uint_as_float((unsigned)(a >> 32)); }

__device__ __forceinline__ float mufu_sin(float r) {
    float s;
    asm("sin.approx.f32 %0, %1;" : "=f"(s) : "f"(r));
    return s;
}
__device__ __forceinline__ float mufu_cos(float r) {
    float c;
    asm("cos.approx.f32 %0, %1;" : "=f"(c) : "f"(r));
    return c;
}

// ---------------- branchless sin(30*u + b30) ----------------
// 5 immediate-form FFMAs (reduction) + 1 MUFU.SIN on r in [-pi/2, pi/2] (+eps)
// + parity sign via XOR. MUFU abs err ~2^-21.4 on reduced range. Fast-math-proof.
__device__ __forceinline__ float sin_omb(float u, float b30) {
    float x  = fmaf(u, OMEGA, b30);
    float nf = fmaf(x, 0.318309886183790672f, 12582912.0f);   // 1.5*2^23 magic
    unsigned nb = __float_as_uint(nf);
    float n  = nf - 12582912.0f;                              // exact rint(x/pi)
    float r  = fmaf(n, -3.140625f,             x);
    r        = fmaf(n, -9.670257568359375e-4f, r);
    r        = fmaf(n, -6.27832957e-7f,        r);
    float s  = mufu_sin(r);
    return __uint_as_float(__float_as_uint(s) ^ (nb << 31));  // flip sign if n odd
}

// ---------------- sincos for positional encoding (same reduction + 2 MUFU) ----------------
__device__ __forceinline__ void sincos_acc(float x, float* so, float* co) {
    float nf = fmaf(x, 0.318309886183790672f, 12582912.0f);
    unsigned sgn = __float_as_uint(nf) << 31;                 // parity of n
    float n  = nf - 12582912.0f;
    float r  = fmaf(n, -3.140625f,             x);
    r        = fmaf(n, -9.670257568359375e-4f, r);
    r        = fmaf(n, -6.27832957e-7f,        r);
    *so = __uint_as_float(__float_as_uint(mufu_sin(r)) ^ sgn);
    *co = __uint_as_float(__float_as_uint(mufu_cos(r)) ^ sgn);
}

// ---------------- 128-wide sine layer ----------------
// out[j][p] = sin(30*(sum_k in[k][p]*W[k][j]) + 30*b[j])
// Warp covers 8 consecutive jg x 4 consecutive pg -> weight LDG.128 span 256B (2 lines),
// act LDS.64 hits 4 distinct 8B on banks {0,8,16,24} (conflict-free broadcast).
template <int K>
__device__ __forceinline__ void big_layer(const float* __restrict__ sInB, float* __restrict__ sOut,
                                          const float* __restrict__ Wg, const float* __restrict__ bg,
                                          int jg, int pg) {
    const float*  ip = sInB + (pg << 3);
    const float4* wp = (const float4*)Wg;   // row k: quads [k*32 + jg*2], [k*32 + jg*2 + 1]
    ull acc[32];
#pragma unroll
    for (int i = 0; i < 32; i++) acc[i] = 0ull;

#pragma unroll 4
    for (int k = 0; k < K; k++) {
        const float* a = ip + k * STR;
        ull ap[4];
        ap[0] = *(const ull*)(a);
        ap[1] = *(const ull*)(a + 2);
        ap[2] = *(const ull*)(a + 4);
        ap[3] = *(const ull*)(a + 6);
        float4 wA = __ldg(wp + k * 32 + (jg << 1));
        float4 wB = __ldg(wp + k * 32 + (jg << 1) + 1);
        ull wq[8];
        wq[0] = dup2(wA.x); wq[1] = dup2(wA.y); wq[2] = dup2(wA.z); wq[3] = dup2(wA.w);
        wq[4] = dup2(wB.x); wq[5] = dup2(wB.y); wq[6] = dup2(wB.z); wq[7] = dup2(wB.w);
#pragma unroll
        for (int jj = 0; jj < 8; jj++)
#pragma unroll
            for (int pp = 0; pp < 4; pp++)
                acc[jj * 4 + pp] = fma2(ap[pp], wq[jj], acc[jj * 4 + pp]);
    }
    __syncthreads();   // all reads of sIn done before anyone overwrites sOut (may alias sIn)

    const int j0 = jg << 3, p0 = pg << 3;
#pragma unroll
    for (int jj = 0; jj < 8; jj++) {
        float b30 = OMEGA * __ldg(bg + j0 + jj);
        float* orow = sOut + (j0 + jj) * STR + p0;
#pragma unroll
        for (int pp = 0; pp < 4; pp++) {
            float v0 = sin_omb(lo2(acc[jj * 4 + pp]), b30);
            float v1 = sin_omb(hi2(acc[jj * 4 + pp]), b30);
            *(ull*)(orow + 2 * pp) = pack2(v0, v1);
        }
    }
    __syncthreads();   // epilogue done before next layer's mainloop overwrites inputs
}

// SMEM floats: sAct 128*STR | sE 78*STR   (~107 KB -> 2 CTAs/SM)
#define SMEM_WORDS ((128 + 78) * STR)

__global__ void __launch_bounds__(NT, 2)
siren_kernel(const float* __restrict__ pts,
             const float* __restrict__ W0, const float* __restrict__ b0,
             const float* __restrict__ W1, const float* __restrict__ b1,
             const float* __restrict__ W2, const float* __restrict__ b2,
             const float* __restrict__ W3, const float* __restrict__ b3,
             const float* __restrict__ W4, const float* __restrict__ b4,
             const float* __restrict__ W5, const float* __restrict__ b5,
             const float* __restrict__ W6, const float* __restrict__ b6,
             const float* __restrict__ W7, const float* __restrict__ b7,
             float* __restrict__ out, int n) {
    extern __shared__ float sm[];
    float* sAct = sm;                    // [128][STR]
    float* sE   = sAct + 128 * STR;      // [78][STR]: rows 0..14 scalar, 15..17 x, 18..77 trig enc

    const int tid = threadIdx.x;
    const int pbase = blockIdx.x * BP;
    const int w = tid >> 5, l = tid & 31;
    const int jg = ((w & 1) << 3) | (l & 7);        // 8 consecutive jg per warp
    const int pg = ((w >> 1) << 2) | (l >> 3);      // 4 consecutive pg per warp

    // ---------------- positional encoding ----------------
    for (int idx = tid; idx < BP * 3; idx += NT) {
        int p = idx / 3, c = idx - 3 * p;
        sE[(15 + c) * STR + p] = pts[pbase * 3 + idx];
    }
    __syncthreads();
    for (int t = tid; t < BP * 30; t += NT) {
        int p = t & (BP - 1);
        int i = t >> 7;                 // 0..29
        int f = i / 3, c = i - 3 * f;
        float freq = 3.14159265358979323846f * (float)(1 << f);
        float ang = sE[(15 + c) * STR + p] * freq;
        float s, co; sincos_acc(ang, &s, &co);
        sE[(18 + 6 * f + c) * STR + p] = s;
        sE[(21 + 6 * f + c) * STR + p] = co;
    }
    __syncthreads();

    // ---------------- L0: enc(63) -> 128 ----------------
    big_layer<63>(sE + 15 * STR, sAct, W0, b0, jg, pg);
    // ---------------- L1..L3: 128 -> 128 ----------------
    big_layer<128>(sAct, sAct, W1, b1, jg, pg);
    big_layer<128>(sAct, sAct, W2, b2, jg, pg);
    big_layer<128>(sAct, sAct, W3, b3, jg, pg);

    // ---------------- L4: 128 -> 16, no activation; j0 -> density, j1..15 -> scalar ----------------
    {
        const int j = tid & 15, pq = tid >> 4;
        const float* ip = sAct + (pq << 3);
        ull a4[4] = {0ull, 0ull, 0ull, 0ull};
#pragma unroll 4
        for (int k = 0; k < 128; k++) {
            const float* a = ip + k * STR;
            ull x0 = *(const ull*)(a);
            ull x1 = *(const ull*)(a + 2);
            ull x2 = *(const ull*)(a + 4);
            ull x3 = *(const ull*)(a + 6);
            ull w4v = dup2(__ldg(W4 + (k << 4) + j));
            a4[0] = fma2(x0, w4v, a4[0]);
            a4[1] = fma2(x1, w4v, a4[1]);
            a4[2] = fma2(x2, w4v, a4[2]);
            a4[3] = fma2(x3, w4v, a4[3]);
        }
        float bj = __ldg(b4 + j);
        if (j == 0) {
            float* od = out + n + pbase + (pq << 3);   // density block
#pragma unroll
            for (int q = 0; q < 4; q++) {
                od[2 * q]     = fmaxf(lo2(a4[q]) + bj, 0.0f);
                od[2 * q + 1] = fmaxf(hi2(a4[q]) + bj, 0.0f);
            }
        } else {
            float* orow = sE + (j - 1) * STR + (pq << 3);   // scalar features, rows 0..14
#pragma unroll
            for (int q = 0; q < 4; q++)
                *(ull*)(orow + 2 * q) = pack2(lo2(a4[q]) + bj, hi2(a4[q]) + bj);
        }
        __syncthreads();
    }

    // ---------------- L5: [scalar(15) | enc(63)] = 78 -> 128 ----------------
    big_layer<78>(sE, sAct, W5, b5, jg, pg);
    // ---------------- L6: 128 -> 128 ----------------
    big_layer<128>(sAct, sAct, W6, b6, jg, pg);

    // ---------------- L7: 128 -> 1 ----------------
    if (tid < BP) {
        float acc = 0.0f;
#pragma unroll 8
        for (int k = 0; k < 128; k++)
            acc = fmaf(sAct[k * STR + tid], __ldg(W7 + k), acc);
        out[pbase + tid] = acc + __ldg(b7);
    }
}

extern "C" void kernel_launch(void* const* d_in, const int* in_sizes, int n_in,
                              void* d_out, int out_size) {
    (void)n_in; (void)out_size;
    const float* pts = (const float*)d_in[0];
    const float* W0 = (const float*)d_in[1];  const float* b0 = (const float*)d_in[2];
    const float* W1 = (const float*)d_in[3];  const float* b1 = (const float*)d_in[4];
    const float* W2 = (const float*)d_in[5];  const float* b2 = (const float*)d_in[6];
    const float* W3 = (const float*)d_in[7];  const float* b3 = (const float*)d_in[8];
    const float* W4 = (const float*)d_in[9];  const float* b4 = (const float*)d_in[10];
    const float* W5 = (const float*)d_in[11]; const float* b5 = (const float*)d_in[12];
    const float* W6 = (const float*)d_in[13]; const float* b6 = (const float*)d_in[14];
    const float* W7 = (const float*)d_in[15]; const float* b7 = (const float*)d_in[16];
    float* out = (float*)d_out;

    int n = in_sizes[0] / 3;
    int blocks = n / BP;
    size_t shmem = (size_t)SMEM_WORDS * sizeof(float);   // ~107 KB -> 2 CTAs/SM

    cudaFuncSetAttribute(siren_kernel, cudaFuncAttributeMaxDynamicSharedMemorySize, (int)shmem);
    siren_kernel<<<blocks, NT, shmem>>>(pts, W0, b0, W1, b1, W2, b2, W3, b3,
                                        W4, b4, W5, b5, W6, b6, W7, b7, out, n);
}

// round 12
// speedup vs baseline: 1.2215x; 1.1639x over previous
#include <cuda_runtime.h>
#include <cuda_bf16.h>
#include <cstdint>

#define NT    256
#define BP    128
#define OMEGA 30.0f
typedef unsigned int uint;
typedef unsigned short ushort;

// SMEM strides (in elements). All chosen so (stride_bytes/4) % 32 ≡ 4 mod 8
// -> 8-row x 4-colpair fragment accesses hit 32 distinct banks.
#define SA 136   // activation tiles, bf16
#define SE 88    // encoding tiles, bf16
#define SW 136   // weight tiles, bf16
#define SF 129   // fp32 final-act scratch

// SMEM byte offsets
#define OFF_AS0 0
#define OFF_AS1 34816
#define OFF_E0  69632
#define OFF_E1  92160
#define OFF_WT0 114688
#define OFF_WT1 149504
#define SMEM_BYTES 184320   // fp32 scratch F (66048B) aliases WT0/WT1

// ---------------- sine: Cody-Waite reduction + MUFU, fast-math-proof ----------------
__device__ __forceinline__ float mufu_sin(float r) { float s; asm("sin.approx.f32 %0, %1;" : "=f"(s) : "f"(r)); return s; }
__device__ __forceinline__ float mufu_cos(float r) { float c; asm("cos.approx.f32 %0, %1;" : "=f"(c) : "f"(r)); return c; }
__device__ __forceinline__ float sin_omb(float u, float b30) {
    float x  = fmaf(u, OMEGA, b30);
    float nf = fmaf(x, 0.318309886183790672f, 12582912.0f);
    unsigned nb = __float_as_uint(nf);
    float n  = nf - 12582912.0f;
    float r  = fmaf(n, -3.140625f, x);
    r = fmaf(n, -9.670257568359375e-4f, r);
    r = fmaf(n, -6.27832957e-7f, r);
    return __uint_as_float(__float_as_uint(mufu_sin(r)) ^ (nb << 31));
}
__device__ __forceinline__ void sincos_acc(float x, float* so, float* co) {
    float nf = fmaf(x, 0.318309886183790672f, 12582912.0f);
    unsigned sgn = __float_as_uint(nf) << 31;
    float n = nf - 12582912.0f;
    float r = fmaf(n, -3.140625f, x);
    r = fmaf(n, -9.670257568359375e-4f, r);
    r = fmaf(n, -6.27832957e-7f, r);
    *so = __uint_as_float(__float_as_uint(mufu_sin(r)) ^ sgn);
    *co = __uint_as_float(__float_as_uint(mufu_cos(r)) ^ sgn);
}

// ---------------- bf16 hi/lo split helpers ----------------
__device__ __forceinline__ void split2(float v0, float v1, uint& hi, uint& lo) {
    __nv_bfloat16 h0 = __float2bfloat16_rn(v0), h1 = __float2bfloat16_rn(v1);
    __nv_bfloat16 l0 = __float2bfloat16_rn(v0 - __bfloat162float(h0));
    __nv_bfloat16 l1 = __float2bfloat16_rn(v1 - __bfloat162float(h1));
    hi = ((uint)__bfloat16_as_ushort(h1) << 16) | __bfloat16_as_ushort(h0);
    lo = ((uint)__bfloat16_as_ushort(l1) << 16) | __bfloat16_as_ushort(l0);
}
__device__ __forceinline__ void stsplit1(ushort* D0, ushort* D1, int idx, float v) {
    __nv_bfloat16 h = __float2bfloat16_rn(v);
    __nv_bfloat16 l = __float2bfloat16_rn(v - __bfloat162float(h));
    D0[idx] = __bfloat16_as_ushort(h);
    D1[idx] = __bfloat16_as_ushort(l);
}

// ---------------- legacy tensor-core MMA (PTX baseline, works on sm_100) ----------------
__device__ __forceinline__ void mma16816(float& c0, float& c1, float& c2, float& c3,
                                         uint a0, uint a1, uint a2, uint a3,
                                         uint b0, uint b1) {
    asm volatile("mma.sync.aligned.m16n8k16.row.col.f32.bf16.bf16.f32 "
                 "{%0,%1,%2,%3}, {%4,%5,%6,%7}, {%8,%9}, {%0,%1,%2,%3};"
                 : "+f"(c0), "+f"(c1), "+f"(c2), "+f"(c3)
                 : "r"(a0), "r"(a1), "r"(a2), "r"(a3), "r"(b0), "r"(b1));
}

// Warp computes C[16 x NTILES*8] over K = KSTEPS*16 with 3-pass bf16 split.
template <int KSTEPS, int NTILES>
__device__ __forceinline__ void run_mma(const ushort* A0, const ushort* A1, int sa,
                                        const ushort* B0, const ushort* B1,
                                        float* acc, int m0, int g, int t2) {
#pragma unroll
    for (int i = 0; i < NTILES * 4; i++) acc[i] = 0.0f;
    for (int pass = 0; pass < 3; pass++) {
        const ushort* A = (pass == 2) ? A1 : A0;
        const ushort* B = (pass == 1) ? B1 : B0;
        for (int k = 0; k < KSTEPS; k++) {
            int k0 = k * 16;
            const ushort* ar = A + (m0 + g) * sa + k0 + t2;
            uint a0 = *(const uint*)ar;            // (row g,   k0+t2..+1)
            uint a1 = *(const uint*)(ar + 8 * sa); // (row g+8, low k)
            uint a2 = *(const uint*)(ar + 8);      // (row g,   high k)
            uint a3 = *(const uint*)(ar + 8 * sa + 8);
#pragma unroll
            for (int nt = 0; nt < NTILES; nt++) {
                const ushort* br = B + (nt * 8 + g) * SW + k0 + t2;
                uint b0 = *(const uint*)br;        // (col g, k rows t2..)
                uint b1 = *(const uint*)(br + 8);  // (col g, k rows t2+8..)
                mma16816(acc[nt * 4], acc[nt * 4 + 1], acc[nt * 4 + 2], acc[nt * 4 + 3],
                         a0, a1, a2, a3, b0, b1);
            }
        }
    }
}

// epilogue: bias+sine, split, store to bf16 pair tiles (own stripe -> no sync needed)
__device__ __forceinline__ void epi_sine(const float* acc, const float* bias,
                                         ushort* D0, ushort* D1, int sd,
                                         int m0, int g, int t2) {
#pragma unroll
    for (int nt = 0; nt < 16; nt++) {
        int c = nt * 8 + t2;
        float ba = OMEGA * __ldg(bias + c), bb = OMEGA * __ldg(bias + c + 1);
        uint hi, lo;
        split2(sin_omb(acc[nt * 4], ba), sin_omb(acc[nt * 4 + 1], bb), hi, lo);
        *(uint*)(D0 + (m0 + g) * sd + c) = hi;
        *(uint*)(D1 + (m0 + g) * sd + c) = lo;
        split2(sin_omb(acc[nt * 4 + 2], ba), sin_omb(acc[nt * 4 + 3], bb), hi, lo);
        *(uint*)(D0 + (m0 + g + 8) * sd + c) = hi;
        *(uint*)(D1 + (m0 + g + 8) * sd + c) = lo;
    }
}

// generic weight transpose+split: WT[j][k] = W[k][j]
__device__ __forceinline__ void conv_wt(char* smp, const float* __restrict__ W, int ldw,
                                        int keff, int kmax2, int tid) {
    ushort* T0 = (ushort*)(smp + OFF_WT0);
    ushort* T1 = (ushort*)(smp + OFF_WT1);
    int j = tid & 127;
    for (int kq = tid >> 7; kq < kmax2; kq += 2) {
        int k = kq * 2;
        float w0 = (k     < keff) ? __ldg(W + (size_t)k * ldw + j)       : 0.0f;
        float w1 = (k + 1 < keff) ? __ldg(W + (size_t)(k + 1) * ldw + j) : 0.0f;
        uint hi, lo; split2(w0, w1, hi, lo);
        *(uint*)(T0 + j * SW + k) = hi;
        *(uint*)(T1 + j * SW + k) = lo;
    }
}
__device__ __forceinline__ float w5_of(const float* __restrict__ W5, int k, int j) {
    if (k < 63)             return __ldg(W5 + (size_t)(15 + k) * 128 + j);  // enc rows
    if (k >= 63 && k < 78)  return __ldg(W5 + (size_t)(k - 63) * 128 + j);  // scalar rows
    return 0.0f;
}
__device__ __forceinline__ void conv_wt5(char* smp, const float* __restrict__ W5, int tid) {
    ushort* T0 = (ushort*)(smp + OFF_WT0);
    ushort* T1 = (ushort*)(smp + OFF_WT1);
    int j = tid & 127;
    for (int kq = tid >> 7; kq < 40; kq += 2) {
        int k = kq * 2;
        uint hi, lo; split2(w5_of(W5, k, j), w5_of(W5, k + 1, j), hi, lo);
        *(uint*)(T0 + j * SW + k) = hi;
        *(uint*)(T1 + j * SW + k) = lo;
    }
}
__device__ __forceinline__ void conv_wt4(char* smp, const float* __restrict__ W4, int tid) {
    ushort* T0 = (ushort*)(smp + OFF_WT0);
    ushort* T1 = (ushort*)(smp + OFF_WT1);
    int j = tid & 15;
    for (int kq = tid >> 4; kq < 64; kq += 16) {
        int k = kq * 2;
        uint hi, lo; split2(__ldg(W4 + k * 16 + j), __ldg(W4 + (k + 1) * 16 + j), hi, lo);
        *(uint*)(T0 + j * SW + k) = hi;
        *(uint*)(T1 + j * SW + k) = lo;
    }
}

__global__ void __launch_bounds__(NT, 1)
siren_mma(const float* __restrict__ pts,
          const float* __restrict__ W0, const float* __restrict__ b0,
          const float* __restrict__ W1, const float* __restrict__ b1,
          const float* __restrict__ W2, const float* __restrict__ b2,
          const float* __restrict__ W3, const float* __restrict__ b3,
          const float* __restrict__ W4, const float* __restrict__ b4,
          const float* __restrict__ W5, const float* __restrict__ b5,
          const float* __restrict__ W6, const float* __restrict__ b6,
          const float* __restrict__ W7, const float* __restrict__ b7,
          float* __restrict__ out, int npts) {
    extern __shared__ char smp[];
    ushort* AS0 = (ushort*)(smp + OFF_AS0);
    ushort* AS1 = (ushort*)(smp + OFF_AS1);
    ushort* E0  = (ushort*)(smp + OFF_E0);
    ushort* E1  = (ushort*)(smp + OFF_E1);
    ushort* WT0 = (ushort*)(smp + OFF_WT0);
    ushort* WT1 = (ushort*)(smp + OFF_WT1);
    float*  F   = (float*)(smp + OFF_WT0);   // fp32 final acts, aliases WT

    const int tid = threadIdx.x, w = tid >> 5, lane = tid & 31;
    const int m0 = w * 16, g = lane >> 2, t2 = (lane & 3) * 2;
    const int pbase = blockIdx.x * BP;

    // ---------------- positional encoding -> E pair (cols 0..62) ----------------
    {
        int m = tid >> 1, h = tid & 1;
        const float* pp = pts + (size_t)(pbase + m) * 3;
        float c3[3] = {__ldg(pp), __ldg(pp + 1), __ldg(pp + 2)};
        if (h == 0)
#pragma unroll
            for (int c = 0; c < 3; c++) stsplit1(E0, E1, m * SE + c, c3[c]);
        for (int f = h * 5; f < h * 5 + 5; f++) {
            float freq = 3.14159265358979323846f * (float)(1 << f);
#pragma unroll
            for (int c = 0; c < 3; c++) {
                float s, co; sincos_acc(c3[c] * freq, &s, &co);
                stsplit1(E0, E1, m * SE + 3 + 6 * f + c, s);
                stsplit1(E0, E1, m * SE + 6 + 6 * f + c, co);
            }
        }
    }
    if (tid < 128) {   // zero pad cols 63 (L0 K-pad), 78, 79 (L5 K-pad)
        E0[tid * SE + 63] = 0; E1[tid * SE + 63] = 0;
        E0[tid * SE + 78] = 0; E1[tid * SE + 78] = 0;
        E0[tid * SE + 79] = 0; E1[tid * SE + 79] = 0;
    }

    float acc[64];

    // ---------------- L0: enc(64 padded) -> 128 ----------------
    conv_wt(smp, W0, 128, 63, 32, tid);
    __syncthreads();
    run_mma<4, 16>(E0, E1, SE, WT0, WT1, acc, m0, g, t2);
    epi_sine(acc, b0, AS0, AS1, SA, m0, g, t2);
    __syncthreads();

    // ---------------- L1..L3: 128 -> 128 ----------------
    {
        const float* Ws[3] = {W1, W2, W3};
        const float* bs[3] = {b1, b2, b3};
        for (int L = 0; L < 3; L++) {
            conv_wt(smp, Ws[L], 128, 128, 64, tid);
            __syncthreads();
            run_mma<8, 16>(AS0, AS1, SA, WT0, WT1, acc, m0, g, t2);
            epi_sine(acc, bs[L], AS0, AS1, SA, m0, g, t2);
            __syncthreads();
        }
    }

    // ---------------- L4: 128 -> 16 (no sine). col0 -> density; cols1..15 -> E 63..77 ----------------
    conv_wt4(smp, W4, tid);
    __syncthreads();
    run_mma<8, 2>(AS0, AS1, SA, WT0, WT1, acc, m0, g, t2);
    {
#pragma unroll
        for (int nt = 0; nt < 2; nt++) {
            int c = nt * 8 + t2;
            float ba = __ldg(b4 + c), bb = __ldg(b4 + c + 1);
            float v0 = acc[nt * 4] + ba,     v1 = acc[nt * 4 + 1] + bb;   // row m0+g
            float v2 = acc[nt * 4 + 2] + ba, v3 = acc[nt * 4 + 3] + bb;   // row m0+g+8
            int r0 = m0 + g, r1 = m0 + g + 8;
            if (c == 0) {
                out[npts + pbase + r0] = fmaxf(v0, 0.0f);
                out[npts + pbase + r1] = fmaxf(v2, 0.0f);
            } else {
                stsplit1(E0, E1, r0 * SE + 62 + c, v0);
                stsplit1(E0, E1, r1 * SE + 62 + c, v2);
            }
            stsplit1(E0, E1, r0 * SE + 62 + c + 1, v1);
            stsplit1(E0, E1, r1 * SE + 62 + c + 1, v3);
        }
    }
    __syncthreads();

    // ---------------- L5: [enc(63)|scalar(15)|pad] = 80 -> 128 ----------------
    conv_wt5(smp, W5, tid);
    __syncthreads();
    run_mma<5, 16>(E0, E1, SE, WT0, WT1, acc, m0, g, t2);
    epi_sine(acc, b5, AS0, AS1, SA, m0, g, t2);
    __syncthreads();

    // ---------------- L6: 128 -> 128, epilogue -> fp32 F (aliases WT region) ----------------
    conv_wt(smp, W6, 128, 128, 64, tid);
    __syncthreads();
    run_mma<8, 16>(AS0, AS1, SA, WT0, WT1, acc, m0, g, t2);
    __syncthreads();   // all warps done reading WT before F overwrites it
    {
#pragma unroll
        for (int nt = 0; nt < 16; nt++) {
            int c = nt * 8 + t2;
            float ba = OMEGA * __ldg(b6 + c), bb = OMEGA * __ldg(b6 + c + 1);
            F[(m0 + g) * SF + c]     = sin_omb(acc[nt * 4],     ba);
            F[(m0 + g) * SF + c + 1] = sin_omb(acc[nt * 4 + 1], bb);
            F[(m0 + g + 8) * SF + c]     = sin_omb(acc[nt * 4 + 2], ba);
            F[(m0 + g + 8) * SF + c + 1] = sin_omb(acc[nt * 4 + 3], bb);
        }
    }
    __syncthreads();

    // ---------------- L7: 128 -> 1 ----------------
    if (tid < BP) {
        float a7 = 0.0f;
#pragma unroll 8
        for (int k = 0; k < 128; k++)
            a7 = fmaf(F[tid * SF + k], __ldg(W7 + k), a7);
        out[pbase + tid] = a7 + __ldg(b7);
    }
}

extern "C" void kernel_launch(void* const* d_in, const int* in_sizes, int n_in,
                              void* d_out, int out_size) {
    (void)n_in; (void)out_size;
    const float* pts = (const float*)d_in[0];
    const float* W0 = (const float*)d_in[1];  const float* b0 = (const float*)d_in[2];
    const float* W1 = (const float*)d_in[3];  const float* b1 = (const float*)d_in[4];
    const float* W2 = (const float*)d_in[5];  const float* b2 = (const float*)d_in[6];
    const float* W3 = (const float*)d_in[7];  const float* b3 = (const float*)d_in[8];
    const float* W4 = (const float*)d_in[9];  const float* b4 = (const float*)d_in[10];
    const float* W5 = (const float*)d_in[11]; const float* b5 = (const float*)d_in[12];
    const float* W6 = (const float*)d_in[13]; const float* b6 = (const float*)d_in[14];
    const float* W7 = (const float*)d_in[15]; const float* b7 = (const float*)d_in[16];
    float* out = (float*)d_out;
    int npts = in_sizes[0] / 3;
    int blocks = npts / BP;
    cudaFuncSetAttribute(siren_mma, cudaFuncAttributeMaxDynamicSharedMemorySize, SMEM_BYTES);
    siren_mma<<<blocks, NT, SMEM_BYTES>>>(pts, W0, b0, W1, b1, W2, b2, W3, b3,
                                          W4, b4, W5, b5, W6, b6, W7, b7, out, npts);
}

// round 13
// speedup vs baseline: 1.3316x; 1.0901x over previous
#include <cuda_runtime.h>
#include <cuda_bf16.h>
#include <cstdint>

#define NT    512
#define BP    128
#define OMEGA 30.0f
typedef unsigned int uint;
typedef unsigned short ushort;

// SMEM strides (elements); stride%64==8 -> conflict-free fragment access
#define SA 136   // activation tiles, bf16
#define SE 88    // encoding tiles, bf16
#define SW 136   // weight tiles, bf16
#define SF 129   // fp32 final-act scratch

#define OFF_AS0 0
#define OFF_AS1 34816
#define OFF_E0  69632
#define OFF_E1  92160
#define OFF_WT0 114688
#define OFF_WT1 149504
#define SMEM_BYTES 184320   // fp32 scratch F aliases WT0/WT1

// ---------------- sine: Cody-Waite reduction + MUFU, fast-math-proof ----------------
__device__ __forceinline__ float mufu_sin(float r) { float s; asm("sin.approx.f32 %0, %1;" : "=f"(s) : "f"(r)); return s; }
__device__ __forceinline__ float mufu_cos(float r) { float c; asm("cos.approx.f32 %0, %1;" : "=f"(c) : "f"(r)); return c; }
__device__ __forceinline__ float sin_omb(float u, float b30) {
    float x  = fmaf(u, OMEGA, b30);
    float nf = fmaf(x, 0.318309886183790672f, 12582912.0f);
    unsigned nb = __float_as_uint(nf);
    float n  = nf - 12582912.0f;
    float r  = fmaf(n, -3.140625f, x);
    r = fmaf(n, -9.670257568359375e-4f, r);
    r = fmaf(n, -6.27832957e-7f, r);
    return __uint_as_float(__float_as_uint(mufu_sin(r)) ^ (nb << 31));
}
__device__ __forceinline__ void sincos_acc(float x, float* so, float* co) {
    float nf = fmaf(x, 0.318309886183790672f, 12582912.0f);
    unsigned sgn = __float_as_uint(nf) << 31;
    float n = nf - 12582912.0f;
    float r = fmaf(n, -3.140625f, x);
    r = fmaf(n, -9.670257568359375e-4f, r);
    r = fmaf(n, -6.27832957e-7f, r);
    *so = __uint_as_float(__float_as_uint(mufu_sin(r)) ^ sgn);
    *co = __uint_as_float(__float_as_uint(mufu_cos(r)) ^ sgn);
}

// ---------------- bf16 hi/lo split helpers ----------------
__device__ __forceinline__ void split2(float v0, float v1, uint& hi, uint& lo) {
    __nv_bfloat16 h0 = __float2bfloat16_rn(v0), h1 = __float2bfloat16_rn(v1);
    __nv_bfloat16 l0 = __float2bfloat16_rn(v0 - __bfloat162float(h0));
    __nv_bfloat16 l1 = __float2bfloat16_rn(v1 - __bfloat162float(h1));
    hi = ((uint)__bfloat16_as_ushort(h1) << 16) | __bfloat16_as_ushort(h0);
    lo = ((uint)__bfloat16_as_ushort(l1) << 16) | __bfloat16_as_ushort(l0);
}
__device__ __forceinline__ void stsplit1(ushort* D0, ushort* D1, int idx, float v) {
    __nv_bfloat16 h = __float2bfloat16_rn(v);
    __nv_bfloat16 l = __float2bfloat16_rn(v - __bfloat162float(h));
    D0[idx] = __bfloat16_as_ushort(h);
    D1[idx] = __bfloat16_as_ushort(l);
}

// ---------------- legacy tensor-core MMA (baseline PTX, works on sm_100) ----------------
__device__ __forceinline__ void mma16816(float& c0, float& c1, float& c2, float& c3,
                                         uint a0, uint a1, uint a2, uint a3,
                                         uint b0, uint b1) {
    asm volatile("mma.sync.aligned.m16n8k16.row.col.f32.bf16.bf16.f32 "
                 "{%0,%1,%2,%3}, {%4,%5,%6,%7}, {%8,%9}, {%0,%1,%2,%3};"
                 : "+f"(c0), "+f"(c1), "+f"(c2), "+f"(c3)
                 : "r"(a0), "r"(a1), "r"(a2), "r"(a3), "r"(b0), "r"(b1));
}

// Warp computes C[16 x NTILES*8] (cols starting at nt0*8) over K=KSTEPS*16, 3-pass split.
template <int KSTEPS, int NTILES>
__device__ __forceinline__ void run_mma(const ushort* A0, const ushort* A1, int sa,
                                        const ushort* B0, const ushort* B1,
                                        float* acc, int m0, int g, int t2, int nt0) {
#pragma unroll
    for (int i = 0; i < NTILES * 4; i++) acc[i] = 0.0f;
    for (int pass = 0; pass < 3; pass++) {
        const ushort* A = (pass == 2) ? A1 : A0;
        const ushort* B = (pass == 1) ? B1 : B0;
        for (int k = 0; k < KSTEPS; k++) {
            int k0 = k * 16;
            const ushort* ar = A + (m0 + g) * sa + k0 + t2;
            uint a0 = *(const uint*)ar;
            uint a1 = *(const uint*)(ar + 8 * sa);
            uint a2 = *(const uint*)(ar + 8);
            uint a3 = *(const uint*)(ar + 8 * sa + 8);
#pragma unroll
            for (int nt = 0; nt < NTILES; nt++) {
                const ushort* br = B + ((nt0 + nt) * 8 + g) * SW + k0 + t2;
                uint b0 = *(const uint*)br;
                uint b1 = *(const uint*)(br + 8);
                mma16816(acc[nt * 4], acc[nt * 4 + 1], acc[nt * 4 + 2], acc[nt * 4 + 3],
                         a0, a1, a2, a3, b0, b1);
            }
        }
    }
}

// epilogue: bias+sine, split, store (warp owns its rows x col-half; no sync needed)
__device__ __forceinline__ void epi_sine(const float* acc, const float* bias,
                                         ushort* D0, ushort* D1, int sd,
                                         int m0, int g, int t2, int nt0) {
#pragma unroll
    for (int nt = 0; nt < 8; nt++) {
        int c = (nt0 + nt) * 8 + t2;
        float ba = OMEGA * __ldg(bias + c), bb = OMEGA * __ldg(bias + c + 1);
        uint hi, lo;
        split2(sin_omb(acc[nt * 4], ba), sin_omb(acc[nt * 4 + 1], bb), hi, lo);
        *(uint*)(D0 + (m0 + g) * sd + c) = hi;
        *(uint*)(D1 + (m0 + g) * sd + c) = lo;
        split2(sin_omb(acc[nt * 4 + 2], ba), sin_omb(acc[nt * 4 + 3], bb), hi, lo);
        *(uint*)(D0 + (m0 + g + 8) * sd + c) = hi;
        *(uint*)(D1 + (m0 + g + 8) * sd + c) = lo;
    }
}

// weight transpose+split: WT[j][k] = W[k][j] (512 threads)
__device__ __forceinline__ void conv_wt(char* smp, const float* __restrict__ W, int ldw,
                                        int keff, int kmax2, int tid) {
    ushort* T0 = (ushort*)(smp + OFF_WT0);
    ushort* T1 = (ushort*)(smp + OFF_WT1);
    int j = tid & 127;
    for (int kq = tid >> 7; kq < kmax2; kq += 4) {
        int k = kq * 2;
        float w0 = (k     < keff) ? __ldg(W + (size_t)k * ldw + j)       : 0.0f;
        float w1 = (k + 1 < keff) ? __ldg(W + (size_t)(k + 1) * ldw + j) : 0.0f;
        uint hi, lo; split2(w0, w1, hi, lo);
        *(uint*)(T0 + j * SW + k) = hi;
        *(uint*)(T1 + j * SW + k) = lo;
    }
}
__device__ __forceinline__ float w5_of(const float* __restrict__ W5, int k, int j) {
    if (k < 63)             return __ldg(W5 + (size_t)(15 + k) * 128 + j);  // enc rows
    if (k >= 63 && k < 78)  return __ldg(W5 + (size_t)(k - 63) * 128 + j);  // scalar rows
    return 0.0f;
}
__device__ __forceinline__ void conv_wt5(char* smp, const float* __restrict__ W5, int tid) {
    ushort* T0 = (ushort*)(smp + OFF_WT0);
    ushort* T1 = (ushort*)(smp + OFF_WT1);
    int j = tid & 127;
    for (int kq = tid >> 7; kq < 40; kq += 4) {
        int k = kq * 2;
        uint hi, lo; split2(w5_of(W5, k, j), w5_of(W5, k + 1, j), hi, lo);
        *(uint*)(T0 + j * SW + k) = hi;
        *(uint*)(T1 + j * SW + k) = lo;
    }
}
__device__ __forceinline__ void conv_wt4(char* smp, const float* __restrict__ W4, int tid) {
    ushort* T0 = (ushort*)(smp + OFF_WT0);
    ushort* T1 = (ushort*)(smp + OFF_WT1);
    int j = tid & 15;
    for (int kq = tid >> 4; kq < 64; kq += 32) {
        int k = kq * 2;
        uint hi, lo; split2(__ldg(W4 + k * 16 + j), __ldg(W4 + (k + 1) * 16 + j), hi, lo);
        *(uint*)(T0 + j * SW + k) = hi;
        *(uint*)(T1 + j * SW + k) = lo;
    }
}

__global__ void __launch_bounds__(NT, 1)
siren_mma(const float* __restrict__ pts,
          const float* __restrict__ W0, const float* __restrict__ b0,
          const float* __restrict__ W1, const float* __restrict__ b1,
          const float* __restrict__ W2, const float* __restrict__ b2,
          const float* __restrict__ W3, const float* __restrict__ b3,
          const float* __restrict__ W4, const float* __restrict__ b4,
          const float* __restrict__ W5, const float* __restrict__ b5,
          const float* __restrict__ W6, const float* __restrict__ b6,
          const float* __restrict__ W7, const float* __restrict__ b7,
          float* __restrict__ out, int npts) {
    extern __shared__ char smp[];
    ushort* AS0 = (ushort*)(smp + OFF_AS0);
    ushort* AS1 = (ushort*)(smp + OFF_AS1);
    ushort* E0  = (ushort*)(smp + OFF_E0);
    ushort* E1  = (ushort*)(smp + OFF_E1);
    ushort* WT0 = (ushort*)(smp + OFF_WT0);
    ushort* WT1 = (ushort*)(smp + OFF_WT1);
    float*  F   = (float*)(smp + OFF_WT0);   // fp32 final acts, aliases WT

    const int tid = threadIdx.x, w = tid >> 5, lane = tid & 31;
    const int m0 = (w >> 1) * 16;            // m-stripe (8 stripes x 16 rows)
    const int wN = w & 1, nt0 = wN * 8;      // column half
    const int g = lane >> 2, t2 = (lane & 3) * 2;
    const int pbase = blockIdx.x * BP;

    // ---------------- positional encoding -> E pair (4 threads/point) ----------------
    {
        int m = tid >> 2, q = tid & 3;
        const float* pp = pts + (size_t)(pbase + m) * 3;
        float c3[3] = {__ldg(pp), __ldg(pp + 1), __ldg(pp + 2)};
        if (q == 3)
#pragma unroll
            for (int c = 0; c < 3; c++) stsplit1(E0, E1, m * SE + c, c3[c]);
#pragma unroll
        for (int ff = 0; ff < 3; ff++) {
            int f = q + ff * 4;
            if (f < 10) {
                float freq = 3.14159265358979323846f * (float)(1 << f);
#pragma unroll
                for (int c = 0; c < 3; c++) {
                    float s, co; sincos_acc(c3[c] * freq, &s, &co);
                    stsplit1(E0, E1, m * SE + 3 + 6 * f + c, s);
                    stsplit1(E0, E1, m * SE + 6 + 6 * f + c, co);
                }
            }
        }
    }
    if (tid < 128) {   // zero pads: col 63 (L0), cols 78, 79 (L5)
        E0[tid * SE + 63] = 0; E1[tid * SE + 63] = 0;
        E0[tid * SE + 78] = 0; E1[tid * SE + 78] = 0;
        E0[tid * SE + 79] = 0; E1[tid * SE + 79] = 0;
    }

    float acc[32];

    // ---------------- L0: enc(64 padded) -> 128 ----------------
    conv_wt(smp, W0, 128, 63, 32, tid);
    __syncthreads();
    run_mma<4, 8>(E0, E1, SE, WT0, WT1, acc, m0, g, t2, nt0);
    epi_sine(acc, b0, AS0, AS1, SA, m0, g, t2, nt0);
    __syncthreads();

    // ---------------- L1..L3: 128 -> 128 ----------------
    {
        const float* Ws[3] = {W1, W2, W3};
        const float* bs[3] = {b1, b2, b3};
        for (int L = 0; L < 3; L++) {
            conv_wt(smp, Ws[L], 128, 128, 64, tid);
            __syncthreads();
            run_mma<8, 8>(AS0, AS1, SA, WT0, WT1, acc, m0, g, t2, nt0);
            epi_sine(acc, bs[L], AS0, AS1, SA, m0, g, t2, nt0);
            __syncthreads();
        }
    }

    // ---------------- L4: 128 -> 16 (wN==0 warps only) ----------------
    conv_wt4(smp, W4, tid);
    __syncthreads();
    if (wN == 0) {
        run_mma<8, 2>(AS0, AS1, SA, WT0, WT1, acc, m0, g, t2, 0);
#pragma unroll
        for (int nt = 0; nt < 2; nt++) {
            int c = nt * 8 + t2;
            float ba = __ldg(b4 + c), bb = __ldg(b4 + c + 1);
            float v0 = acc[nt * 4] + ba,     v1 = acc[nt * 4 + 1] + bb;   // row m0+g
            float v2 = acc[nt * 4 + 2] + ba, v3 = acc[nt * 4 + 3] + bb;   // row m0+g+8
            int r0 = m0 + g, r1 = m0 + g + 8;
            if (c == 0) {
                out[npts + pbase + r0] = fmaxf(v0, 0.0f);
                out[npts + pbase + r1] = fmaxf(v2, 0.0f);
            } else {
                stsplit1(E0, E1, r0 * SE + 62 + c, v0);
                stsplit1(E0, E1, r1 * SE + 62 + c, v2);
            }
            stsplit1(E0, E1, r0 * SE + 62 + c + 1, v1);
            stsplit1(E0, E1, r1 * SE + 62 + c + 1, v3);
        }
    }
    __syncthreads();

    // ---------------- L5: [enc(63)|scalar(15)|pad] = 80 -> 128 ----------------
    conv_wt5(smp, W5, tid);
    __syncthreads();
    run_mma<5, 8>(E0, E1, SE, WT0, WT1, acc, m0, g, t2, nt0);
    epi_sine(acc, b5, AS0, AS1, SA, m0, g, t2, nt0);
    __syncthreads();

    // ---------------- L6: 128 -> 128, epilogue -> fp32 F (aliases WT) ----------------
    conv_wt(smp, W6, 128, 128, 64, tid);
    __syncthreads();
    run_mma<8, 8>(AS0, AS1, SA, WT0, WT1, acc, m0, g, t2, nt0);
    __syncthreads();   // all warps done reading WT before F overwrites it
#pragma unroll
    for (int nt = 0; nt < 8; nt++) {
        int c = (nt0 + nt) * 8 + t2;
        float ba = OMEGA * __ldg(b6 + c), bb = OMEGA * __ldg(b6 + c + 1);
        F[(m0 + g) * SF + c]     = sin_omb(acc[nt * 4],     ba);
        F[(m0 + g) * SF + c + 1] = sin_omb(acc[nt * 4 + 1], bb);
        F[(m0 + g + 8) * SF + c]     = sin_omb(acc[nt * 4 + 2], ba);
        F[(m0 + g + 8) * SF + c + 1] = sin_omb(acc[nt * 4 + 3], bb);
    }
    __syncthreads();

    // ---------------- L7: 128 -> 1 ----------------
    if (tid < BP) {
        float a7 = 0.0f;
#pragma unroll 8
        for (int k = 0; k < 128; k++)
            a7 = fmaf(F[tid * SF + k], __ldg(W7 + k), a7);
        out[pbase + tid] = a7 + __ldg(b7);
    }
}

extern "C" void kernel_launch(void* const* d_in, const int* in_sizes, int n_in,
                              void* d_out, int out_size) {
    (void)n_in; (void)out_size;
    const float* pts = (const float*)d_in[0];
    const float* W0 = (const float*)d_in[1];  const float* b0 = (const float*)d_in[2];
    const float* W1 = (const float*)d_in[3];  const float* b1 = (const float*)d_in[4];
    const float* W2 = (const float*)d_in[5];  const float* b2 = (const float*)d_in[6];
    const float* W3 = (const float*)d_in[7];  const float* b3 = (const float*)d_in[8];
    const float* W4 = (const float*)d_in[9];  const float* b4 = (const float*)d_in[10];
    const float* W5 = (const float*)d_in[11]; const float* b5 = (const float*)d_in[12];
    const float* W6 = (const float*)d_in[13]; const float* b6 = (const float*)d_in[14];
    const float* W7 = (const float*)d_in[15]; const float* b7 = (const float*)d_in[16];
    float* out = (float*)d_out;
    int npts = in_sizes[0] / 3;
    int blocks = npts / BP;
    cudaFuncSetAttribute(siren_mma, cudaFuncAttributeMaxDynamicSharedMemorySize, SMEM_BYTES);
    siren_mma<<<blocks, NT, SMEM_BYTES>>>(pts, W0, b0, W1, b1, W2, b2, W3, b3,
                                          W4, b4, W5, b5, W6, b6, W7, b7, out, npts);
}

// round 17
// speedup vs baseline: 1.4177x; 1.0646x over previous
#include <cuda_runtime.h>
#include <cuda_bf16.h>
#include <cstdint>

#define NT    512
#define BP    128
#define OMEGA 30.0f
typedef unsigned int uint;
typedef unsigned short ushort;

// SMEM strides (elements); stride%64==8 -> conflict-free fragment access
#define SA 136   // activation tiles, bf16
#define SE 88    // encoding tiles, bf16
#define SW 136   // weight tiles, bf16
#define SF 129   // fp32 final-act scratch

#define OFF_AS0 0
#define OFF_AS1 34816
#define OFF_E0  69632
#define OFF_E1  92160
#define OFF_WT0 114688
#define OFF_WT1 149504
#define SMEM_BYTES 184320   // fp32 scratch F aliases WT0/WT1

// ---------------- sine: Cody-Waite reduction + MUFU, fast-math-proof ----------------
__device__ __forceinline__ float mufu_sin(float r) { float s; asm("sin.approx.f32 %0, %1;" : "=f"(s) : "f"(r)); return s; }
__device__ __forceinline__ float mufu_cos(float r) { float c; asm("cos.approx.f32 %0, %1;" : "=f"(c) : "f"(r)); return c; }
__device__ __forceinline__ float sin_omb(float u, float b30) {
    float x  = fmaf(u, OMEGA, b30);
    float nf = fmaf(x, 0.318309886183790672f, 12582912.0f);
    unsigned nb = __float_as_uint(nf);
    float n  = nf - 12582912.0f;
    float r  = fmaf(n, -3.140625f, x);
    r = fmaf(n, -9.670257568359375e-4f, r);
    r = fmaf(n, -6.27832957e-7f, r);
    return __uint_as_float(__float_as_uint(mufu_sin(r)) ^ (nb << 31));
}
__device__ __forceinline__ void sincos_acc(float x, float* so, float* co) {
    float nf = fmaf(x, 0.318309886183790672f, 12582912.0f);
    unsigned sgn = __float_as_uint(nf) << 31;
    float n = nf - 12582912.0f;
    float r = fmaf(n, -3.140625f, x);
    r = fmaf(n, -9.670257568359375e-4f, r);
    r = fmaf(n, -6.27832957e-7f, r);
    *so = __uint_as_float(__float_as_uint(mufu_sin(r)) ^ sgn);
    *co = __uint_as_float(__float_as_uint(mufu_cos(r)) ^ sgn);
}

// ---------------- bf16 hi/lo split helpers ----------------
__device__ __forceinline__ void split2(float v0, float v1, uint& hi, uint& lo) {
    __nv_bfloat16 h0 = __float2bfloat16_rn(v0), h1 = __float2bfloat16_rn(v1);
    __nv_bfloat16 l0 = __float2bfloat16_rn(v0 - __bfloat162float(h0));
    __nv_bfloat16 l1 = __float2bfloat16_rn(v1 - __bfloat162float(h1));
    hi = ((uint)__bfloat16_as_ushort(h1) << 16) | __bfloat16_as_ushort(h0);
    lo = ((uint)__bfloat16_as_ushort(l1) << 16) | __bfloat16_as_ushort(l0);
}
__device__ __forceinline__ void stsplit1(ushort* D0, ushort* D1, int idx, float v) {
    __nv_bfloat16 h = __float2bfloat16_rn(v);
    __nv_bfloat16 l = __float2bfloat16_rn(v - __bfloat162float(h));
    D0[idx] = __bfloat16_as_ushort(h);
    D1[idx] = __bfloat16_as_ushort(l);
}

// ---------------- legacy tensor-core MMA (baseline PTX, works on sm_100) ----------------
__device__ __forceinline__ void mma16816(float& c0, float& c1, float& c2, float& c3,
                                         uint a0, uint a1, uint a2, uint a3,
                                         uint b0, uint b1) {
    asm volatile("mma.sync.aligned.m16n8k16.row.col.f32.bf16.bf16.f32 "
                 "{%0,%1,%2,%3}, {%4,%5,%6,%7}, {%8,%9}, {%0,%1,%2,%3};"
                 : "+f"(c0), "+f"(c1), "+f"(c2), "+f"(c3)
                 : "r"(a0), "r"(a1), "r"(a2), "r"(a3), "r"(b0), "r"(b1));
}

// Warp computes C[16 x NTILES*8] (cols from nt0*8) over K=KSTEPS*16.
// k-outer 3-term split: per k load A0,A1 frags once, B0 frags -> A0B0 + A1B0,
// reload B1 frags -> A0B1. Scalar fragment loads (R13-proven addressing).
template <int KSTEPS, int NTILES>
__device__ __forceinline__ void run_mma(const ushort* A0, const ushort* A1, int sa,
                                        const ushort* B0, const ushort* B1,
                                        float* acc, int m0, int g, int t2, int nt0) {
#pragma unroll
    for (int i = 0; i < NTILES * 4; i++) acc[i] = 0.0f;
    for (int k = 0; k < KSTEPS; k++) {
        int k0 = k * 16;
        // A fragments: hi (p) and lo (q)
        const ushort* ar = A0 + (m0 + g) * sa + k0 + t2;
        uint p0 = *(const uint*)ar;
        uint p1 = *(const uint*)(ar + 8 * sa);
        uint p2 = *(const uint*)(ar + 8);
        uint p3 = *(const uint*)(ar + 8 * sa + 8);
        const ushort* qr = A1 + (m0 + g) * sa + k0 + t2;
        uint q0 = *(const uint*)qr;
        uint q1 = *(const uint*)(qr + 8 * sa);
        uint q2 = *(const uint*)(qr + 8);
        uint q3 = *(const uint*)(qr + 8 * sa + 8);
        // B0 fragments for all tiles
        uint bf[NTILES * 2];
#pragma unroll
        for (int nt = 0; nt < NTILES; nt++) {
            const ushort* br = B0 + ((nt0 + nt) * 8 + g) * SW + k0 + t2;
            bf[2 * nt]     = *(const uint*)br;
            bf[2 * nt + 1] = *(const uint*)(br + 8);
        }
#pragma unroll
        for (int nt = 0; nt < NTILES; nt++) {
            mma16816(acc[nt*4], acc[nt*4+1], acc[nt*4+2], acc[nt*4+3],
                     p0, p1, p2, p3, bf[2*nt], bf[2*nt+1]);
            mma16816(acc[nt*4], acc[nt*4+1], acc[nt*4+2], acc[nt*4+3],
                     q0, q1, q2, q3, bf[2*nt], bf[2*nt+1]);
        }
        // B1 fragments, reuse p (A-hi)
#pragma unroll
        for (int nt = 0; nt < NTILES; nt++) {
            const ushort* br = B1 + ((nt0 + nt) * 8 + g) * SW + k0 + t2;
            bf[2 * nt]     = *(const uint*)br;
            bf[2 * nt + 1] = *(const uint*)(br + 8);
        }
#pragma unroll
        for (int nt = 0; nt < NTILES; nt++) {
            mma16816(acc[nt*4], acc[nt*4+1], acc[nt*4+2], acc[nt*4+3],
                     p0, p1, p2, p3, bf[2*nt], bf[2*nt+1]);
        }
    }
}

// epilogue: bias+sine, split, store (warp owns rows x col-half)
__device__ __forceinline__ void epi_sine(const float* acc, const float* bias,
                                         ushort* D0, ushort* D1, int sd,
                                         int m0, int g, int t2, int nt0) {
#pragma unroll
    for (int nt = 0; nt < 8; nt++) {
        int c = (nt0 + nt) * 8 + t2;
        float ba = OMEGA * __ldg(bias + c), bb = OMEGA * __ldg(bias + c + 1);
        uint hi, lo;
        split2(sin_omb(acc[nt * 4], ba), sin_omb(acc[nt * 4 + 1], bb), hi, lo);
        *(uint*)(D0 + (m0 + g) * sd + c) = hi;
        *(uint*)(D1 + (m0 + g) * sd + c) = lo;
        split2(sin_omb(acc[nt * 4 + 2], ba), sin_omb(acc[nt * 4 + 3], bb), hi, lo);
        *(uint*)(D0 + (m0 + g + 8) * sd + c) = hi;
        *(uint*)(D1 + (m0 + g + 8) * sd + c) = lo;
    }
}

// weight transpose+split: WT[j][k] = W[k][j] (512 threads)
__device__ __forceinline__ void conv_wt(char* smp, const float* __restrict__ W, int ldw,
                                        int keff, int kmax2, int tid) {
    ushort* T0 = (ushort*)(smp + OFF_WT0);
    ushort* T1 = (ushort*)(smp + OFF_WT1);
    int j = tid & 127;
    for (int kq = tid >> 7; kq < kmax2; kq += 4) {
        int k = kq * 2;
        float w0 = (k     < keff) ? __ldg(W + (size_t)k * ldw + j)       : 0.0f;
        float w1 = (k + 1 < keff) ? __ldg(W + (size_t)(k + 1) * ldw + j) : 0.0f;
        uint hi, lo; split2(w0, w1, hi, lo);
        *(uint*)(T0 + j * SW + k) = hi;
        *(uint*)(T1 + j * SW + k) = lo;
    }
}
__device__ __forceinline__ float w5_of(const float* __restrict__ W5, int k, int j) {
    if (k < 63)             return __ldg(W5 + (size_t)(15 + k) * 128 + j);  // enc rows
    if (k >= 63 && k < 78)  return __ldg(W5 + (size_t)(k - 63) * 128 + j);  // scalar rows
    return 0.0f;
}
__device__ __forceinline__ void conv_wt5(char* smp, const float* __restrict__ W5, int tid) {
    ushort* T0 = (ushort*)(smp + OFF_WT0);
    ushort* T1 = (ushort*)(smp + OFF_WT1);
    int j = tid & 127;
    for (int kq = tid >> 7; kq < 40; kq += 4) {
        int k = kq * 2;
        uint hi, lo; split2(w5_of(W5, k, j), w5_of(W5, k + 1, j), hi, lo);
        *(uint*)(T0 + j * SW + k) = hi;
        *(uint*)(T1 + j * SW + k) = lo;
    }
}
__device__ __forceinline__ void conv_wt4(char* smp, const float* __restrict__ W4, int tid) {
    ushort* T0 = (ushort*)(smp + OFF_WT0);
    ushort* T1 = (ushort*)(smp + OFF_WT1);
    int j = tid & 15;
    for (int kq = tid >> 4; kq < 64; kq += 32) {
        int k = kq * 2;
        uint hi, lo; split2(__ldg(W4 + k * 16 + j), __ldg(W4 + (k + 1) * 16 + j), hi, lo);
        *(uint*)(T0 + j * SW + k) = hi;
        *(uint*)(T1 + j * SW + k) = lo;
    }
}

__global__ void __launch_bounds__(NT, 1)
siren_mma(const float* __restrict__ pts,
          const float* __restrict__ W0, const float* __restrict__ b0,
          const float* __restrict__ W1, const float* __restrict__ b1,
          const float* __restrict__ W2, const float* __restrict__ b2,
          const float* __restrict__ W3, const float* __restrict__ b3,
          const float* __restrict__ W4, const float* __restrict__ b4,
          const float* __restrict__ W5, const float* __restrict__ b5,
          const float* __restrict__ W6, const float* __restrict__ b6,
          const float* __restrict__ W7, const float* __restrict__ b7,
          float* __restrict__ out, int npts) {
    extern __shared__ char smp[];
    ushort* AS0 = (ushort*)(smp + OFF_AS0);
    ushort* AS1 = (ushort*)(smp + OFF_AS1);
    ushort* E0  = (ushort*)(smp + OFF_E0);
    ushort* E1  = (ushort*)(smp + OFF_E1);
    ushort* WT0 = (ushort*)(smp + OFF_WT0);
    ushort* WT1 = (ushort*)(smp + OFF_WT1);
    float*  F   = (float*)(smp + OFF_WT0);   // fp32 final acts, aliases WT

    const int tid = threadIdx.x, w = tid >> 5, lane = tid & 31;
    const int m0 = (w >> 1) * 16;            // m-stripe (8 stripes x 16 rows)
    const int wN = w & 1, nt0 = wN * 8;      // column half
    const int g = lane >> 2, t2 = (lane & 3) * 2;
    const int pbase = blockIdx.x * BP;

    // ---------------- positional encoding -> E pair (4 threads/point) ----------------
    {
        int m = tid >> 2, q = tid & 3;
        const float* pp = pts + (size_t)(pbase + m) * 3;
        float c3[3] = {__ldg(pp), __ldg(pp + 1), __ldg(pp + 2)};
        if (q == 3)
#pragma unroll
            for (int c = 0; c < 3; c++) stsplit1(E0, E1, m * SE + c, c3[c]);
#pragma unroll
        for (int ff = 0; ff < 3; ff++) {
            int f = q + ff * 4;
            if (f < 10) {
                float freq = 3.14159265358979323846f * (float)(1 << f);
#pragma unroll
                for (int c = 0; c < 3; c++) {
                    float s, co; sincos_acc(c3[c] * freq, &s, &co);
                    stsplit1(E0, E1, m * SE + 3 + 6 * f + c, s);
                    stsplit1(E0, E1, m * SE + 6 + 6 * f + c, co);
                }
            }
        }
    }
    if (tid < 128) {   // zero pads: col 63 (L0), cols 78, 79 (L5)
        E0[tid * SE + 63] = 0; E1[tid * SE + 63] = 0;
        E0[tid * SE + 78] = 0; E1[tid * SE + 78] = 0;
        E0[tid * SE + 79] = 0; E1[tid * SE + 79] = 0;
    }

    float acc[32];

    // ---------------- L0: enc(64 padded) -> 128 (E -> AS, no alias) ----------------
    conv_wt(smp, W0, 128, 63, 32, tid);
    __syncthreads();
    run_mma<4, 8>(E0, E1, SE, WT0, WT1, acc, m0, g, t2, nt0);
    epi_sine(acc, b0, AS0, AS1, SA, m0, g, t2, nt0);
    __syncthreads();

    // ---------------- L1..L3: 128 -> 128 (AS -> AS, IN-PLACE: sync before epi!) ------
    // Warp pairs share stripe rows; partner's run_mma reads ALL columns of those rows,
    // so epilogue writes must wait for both warps' mainloops to finish.
    {
        const float* Ws[3] = {W1, W2, W3};
        const float* bs[3] = {b1, b2, b3};
        for (int L = 0; L < 3; L++) {
            conv_wt(smp, Ws[L], 128, 128, 64, tid);
            __syncthreads();
            run_mma<8, 8>(AS0, AS1, SA, WT0, WT1, acc, m0, g, t2, nt0);
            __syncthreads();   // RACE FIX: all reads of AS done before epi overwrites
            epi_sine(acc, bs[L], AS0, AS1, SA, m0, g, t2, nt0);
            __syncthreads();
        }
    }

    // ---------------- L4: 128 -> 16 (wN==0 warps only; writes E, no alias) ----------
    conv_wt4(smp, W4, tid);
    __syncthreads();
    if (wN == 0) {
        run_mma<8, 2>(AS0, AS1, SA, WT0, WT1, acc, m0, g, t2, 0);
#pragma unroll
        for (int nt = 0; nt < 2; nt++) {
            int c = nt * 8 + t2;
            float ba = __ldg(b4 + c), bb = __ldg(b4 + c + 1);
            float v0 = acc[nt * 4] + ba,     v1 = acc[nt * 4 + 1] + bb;   // row m0+g
            float v2 = acc[nt * 4 + 2] + ba, v3 = acc[nt * 4 + 3] + bb;   // row m0+g+8
            int r0 = m0 + g, r1 = m0 + g + 8;
            if (c == 0) {
                out[npts + pbase + r0] = fmaxf(v0, 0.0f);
                out[npts + pbase + r1] = fmaxf(v2, 0.0f);
            } else {
                stsplit1(E0, E1, r0 * SE + 62 + c, v0);
                stsplit1(E0, E1, r1 * SE + 62 + c, v2);
            }
            stsplit1(E0, E1, r0 * SE + 62 + c + 1, v1);
            stsplit1(E0, E1, r1 * SE + 62 + c + 1, v3);
        }
    }
    __syncthreads();

    // ---------------- L5: [enc(63)|scalar(15)|pad] = 80 -> 128 (E -> AS, no alias) --
    conv_wt5(smp, W5, tid);
    __syncthreads();
    run_mma<5, 8>(E0, E1, SE, WT0, WT1, acc, m0, g, t2, nt0);
    epi_sine(acc, b5, AS0, AS1, SA, m0, g, t2, nt0);
    __syncthreads();

    // ---------------- L6: 128 -> 128, epilogue -> fp32 F (aliases WT; sync'd) -------
    conv_wt(smp, W6, 128, 128, 64, tid);
    __syncthreads();
    run_mma<8, 8>(AS0, AS1, SA, WT0, WT1, acc, m0, g, t2, nt0);
    __syncthreads();   // all warps done reading WT before F overwrites it
#pragma unroll
    for (int nt = 0; nt < 8; nt++) {
        int c = (nt0 + nt) * 8 + t2;
        float ba = OMEGA * __ldg(b6 + c), bb = OMEGA * __ldg(b6 + c + 1);
        F[(m0 + g) * SF + c]     = sin_omb(acc[nt * 4],     ba);
        F[(m0 + g) * SF + c + 1] = sin_omb(acc[nt * 4 + 1], bb);
        F[(m0 + g + 8) * SF + c]     = sin_omb(acc[nt * 4 + 2], ba);
        F[(m0 + g + 8) * SF + c + 1] = sin_omb(acc[nt * 4 + 3], bb);
    }
    __syncthreads();

    // ---------------- L7: 128 -> 1 ----------------
    if (tid < BP) {
        float a7 = 0.0f;
#pragma unroll 8
        for (int k = 0; k < 128; k++)
            a7 = fmaf(F[tid * SF + k], __ldg(W7 + k), a7);
        out[pbase + tid] = a7 + __ldg(b7);
    }
}

extern "C" void kernel_launch(void* const* d_in, const int* in_sizes, int n_in,
                              void* d_out, int out_size) {
    (void)n_in; (void)out_size;
    const float* pts = (const float*)d_in[0];
    const float* W0 = (const float*)d_in[1];  const float* b0 = (const float*)d_in[2];
    const float* W1 = (const float*)d_in[3];  const float* b1 = (const float*)d_in[4];
    const float* W2 = (const float*)d_in[5];  const float* b2 = (const float*)d_in[6];
    const float* W3 = (const float*)d_in[7];  const float* b3 = (const float*)d_in[8];
    const float* W4 = (const float*)d_in[9];  const float* b4 = (const float*)d_in[10];
    const float* W5 = (const float*)d_in[11]; const float* b5 = (const float*)d_in[12];
    const float* W6 = (const float*)d_in[13]; const float* b6 = (const float*)d_in[14];
    const float* W7 = (const float*)d_in[15]; const float* b7 = (const float*)d_in[16];
    float* out = (float*)d_out;
    int npts = in_sizes[0] / 3;
    int blocks = npts / BP;
    cudaFuncSetAttribute(siren_mma, cudaFuncAttributeMaxDynamicSharedMemorySize, SMEM_BYTES);
    siren_mma<<<blocks, NT, SMEM_BYTES>>>(pts, W0, b0, W1, b1, W2, b2, W3, b3,
                                          W4, b4, W5, b5, W6, b6, W7, b7, out, npts);
}